// round 2
// baseline (speedup 1.0000x reference)
#include <cuda_runtime.h>

// LIF scan, bit-faithful to the reference per-op rounding:
//   v_euler = v + ((-v + 3000*I) / 150) * 0.01   (each op RN-rounded; div via
//   Markstein 3-op refinement == div.rn.f32)
//   v = (v >= 15) ? 0 : v_euler ; v = (v >= 15) ? 30 : v
// Carried-predicate invariant: entering any step v is exactly 30 or < 15, so the
// reset predicate equals the previous step's spike predicate (one compare/step).

#define UNROLL_T 8
#define T_STEPS 1000
#define N_NEUR 131072
#define N4 (N_NEUR / 4)  // float4 quads per timestep = 32768

__device__ __forceinline__ void lif_step(float& v, bool& p, float I) {
    const float y = (float)(1.0 / 150.0);        // RN(1/150)
    float pr  = __fmul_rn(I, 3000.0f);
    float num = __fadd_rn(pr, -v);
    float q0  = __fmul_rn(num, y);
    float rr  = __fmaf_rn(q0, -150.0f, num);     // exact remainder (FMA)
    float q   = __fmaf_rn(rr, y, q0);            // correctly rounded num/150
    float dv  = __fmul_rn(q, 0.01f);
    float ve  = __fadd_rn(v, dv);
    bool spike = (ve >= 15.0f) && (!p);
    float tv = p ? 0.0f : ve;
    v = spike ? 30.0f : tv;
    p = spike;
}

__device__ __forceinline__ void lif_step4(float4& v, bool* p, const float4& I) {
    lif_step(v.x, p[0], I.x);
    lif_step(v.y, p[1], I.y);
    lif_step(v.z, p[2], I.z);
    lif_step(v.w, p[3], I.w);
}

__global__ void __launch_bounds__(64)
lif_kernel_fixed(const float4* __restrict__ stim, float4* __restrict__ out) {
    const int idx = blockIdx.x * 64 + threadIdx.x;     // quad index 0..N4-1
    const float4* __restrict__ sp = stim + idx;
    float4* __restrict__ op = out + idx;

    float4 v = make_float4(0.f, 0.f, 0.f, 0.f);
    bool p[4] = {false, false, false, false};

    const size_t row   = (size_t)N4;                   // quads per timestep
    const size_t chunk = (size_t)UNROLL_T * row;

    float4 buf[UNROLL_T];
    #pragma unroll
    for (int u = 0; u < UNROLL_T; u++) buf[u] = __ldcs(sp + (size_t)u * row);

    const float4* __restrict__ ld = sp + chunk;
    float4* __restrict__ st = op;

    const int nchunks = T_STEPS / UNROLL_T;            // 125

    for (int c = 0; c < nchunks - 1; c++) {
        float4 nbuf[UNROLL_T];
        // Prefetch next chunk: 8 independent LDG.128.STRM in flight
        #pragma unroll
        for (int u = 0; u < UNROLL_T; u++) nbuf[u] = __ldcs(ld + (size_t)u * row);
        // Compute + stream-store current chunk
        #pragma unroll
        for (int u = 0; u < UNROLL_T; u++) {
            lif_step4(v, p, buf[u]);
            __stcs(st + (size_t)u * row, v);
        }
        #pragma unroll
        for (int u = 0; u < UNROLL_T; u++) buf[u] = nbuf[u];
        ld += chunk;
        st += chunk;
    }
    #pragma unroll
    for (int u = 0; u < UNROLL_T; u++) {
        lif_step4(v, p, buf[u]);
        __stcs(st + (size_t)u * row, v);
    }
}

// Generic fallback (any N, T=1000 assumed) — correctness path for odd shapes.
__global__ void lif_kernel_generic(const float* __restrict__ stim,
                                   float* __restrict__ out, int N, int T) {
    int n = blockIdx.x * blockDim.x + threadIdx.x;
    if (n >= N) return;
    float v = 0.0f;
    bool p = false;
    for (int t = 0; t < T; t++) {
        lif_step(v, p, stim[(size_t)t * N + n]);
        out[(size_t)t * N + n] = v;
    }
}

extern "C" void kernel_launch(void* const* d_in, const int* in_sizes, int n_in,
                              void* d_out, int out_size) {
    const float* stim = (const float*)d_in[0];
    float* out = (float*)d_out;

    if (in_sizes[0] == T_STEPS * N_NEUR && out_size == T_STEPS * N_NEUR) {
        // 32768 quads / 64 threads = 512 blocks
        lif_kernel_fixed<<<N4 / 64, 64>>>((const float4*)stim, (float4*)out);
    } else {
        int T = 1000;
        int N = in_sizes[0] / T;
        int threads = 128;
        int blocks = (N + threads - 1) / threads;
        lif_kernel_generic<<<blocks, threads>>>(stim, out, N, T);
    }
}

// round 3
// speedup vs baseline: 1.1194x; 1.1194x over previous
#include <cuda_runtime.h>

// LIF scan, bit-faithful to the reference per-op rounding:
//   v_euler = v + ((-v + 3000*I) / 150) * 0.01   (each op RN-rounded; div via
//   Markstein 3-op refinement == div.rn.f32)
//   v = (v >= 15) ? 0 : v_euler ; v = (v >= 15) ? 30 : v
// Carried-predicate invariant: entering any step v is exactly 30 or < 15, so the
// reset predicate equals the previous step's spike predicate (one compare/step).
//
// R3 shape: float2 lanes (256 B/warp accesses), 64-thr blocks x 1024 blocks
// (6.9 CTAs/SM, single wave, ~14 warps/SM), UNROLL_T=10 double-buffered
// prefetch (~33.5 KB in flight/SM), streaming cache ops on both streams.

#define UNROLL_T 10
#define T_STEPS 1000
#define N_NEUR 131072
#define N2 (N_NEUR / 2)  // float2 pairs per timestep = 65536

__device__ __forceinline__ void lif_step(float& v, bool& p, float I) {
    const float y = (float)(1.0 / 150.0);        // RN(1/150)
    float pr  = __fmul_rn(I, 3000.0f);
    float num = __fadd_rn(pr, -v);
    float q0  = __fmul_rn(num, y);
    float rr  = __fmaf_rn(q0, -150.0f, num);     // exact remainder (FMA)
    float q   = __fmaf_rn(rr, y, q0);            // correctly rounded num/150
    float dv  = __fmul_rn(q, 0.01f);
    float ve  = __fadd_rn(v, dv);
    bool spike = (ve >= 15.0f) && (!p);
    float tv = p ? 0.0f : ve;
    v = spike ? 30.0f : tv;
    p = spike;
}

__global__ void __launch_bounds__(64, 7)
lif_kernel_fixed(const float2* __restrict__ stim, float2* __restrict__ out) {
    const int idx = blockIdx.x * 64 + threadIdx.x;     // pair index 0..N2-1
    const float2* __restrict__ sp = stim + idx;
    float2* __restrict__ op = out + idx;

    float v0 = 0.0f, v1 = 0.0f;
    bool p0 = false, p1 = false;

    const size_t row   = (size_t)N2;                   // pairs per timestep
    const size_t chunk = (size_t)UNROLL_T * row;

    float2 buf[UNROLL_T];
    #pragma unroll
    for (int u = 0; u < UNROLL_T; u++) buf[u] = __ldcs(sp + (size_t)u * row);

    const float2* __restrict__ ld = sp + chunk;
    float2* __restrict__ st = op;

    const int nchunks = T_STEPS / UNROLL_T;            // 100

    for (int c = 0; c < nchunks - 1; c++) {
        float2 nbuf[UNROLL_T];
        // Prefetch next chunk: 10 independent LDG.64.STRM in flight
        #pragma unroll
        for (int u = 0; u < UNROLL_T; u++) nbuf[u] = __ldcs(ld + (size_t)u * row);
        // Compute + stream-store current chunk
        #pragma unroll
        for (int u = 0; u < UNROLL_T; u++) {
            lif_step(v0, p0, buf[u].x);
            lif_step(v1, p1, buf[u].y);
            __stcs(st + (size_t)u * row, make_float2(v0, v1));
        }
        #pragma unroll
        for (int u = 0; u < UNROLL_T; u++) buf[u] = nbuf[u];
        ld += chunk;
        st += chunk;
    }
    #pragma unroll
    for (int u = 0; u < UNROLL_T; u++) {
        lif_step(v0, p0, buf[u].x);
        lif_step(v1, p1, buf[u].y);
        __stcs(st + (size_t)u * row, make_float2(v0, v1));
    }
}

// Generic fallback (any N, T=1000 assumed) — correctness path for odd shapes.
__global__ void lif_kernel_generic(const float* __restrict__ stim,
                                   float* __restrict__ out, int N, int T) {
    int n = blockIdx.x * blockDim.x + threadIdx.x;
    if (n >= N) return;
    float v = 0.0f;
    bool p = false;
    for (int t = 0; t < T; t++) {
        lif_step(v, p, stim[(size_t)t * N + n]);
        out[(size_t)t * N + n] = v;
    }
}

extern "C" void kernel_launch(void* const* d_in, const int* in_sizes, int n_in,
                              void* d_out, int out_size) {
    const float* stim = (const float*)d_in[0];
    float* out = (float*)d_out;

    if (in_sizes[0] == T_STEPS * N_NEUR && out_size == T_STEPS * N_NEUR) {
        // 65536 pairs / 64 threads = 1024 blocks (one full wave on 148 SMs)
        lif_kernel_fixed<<<N2 / 64, 64>>>((const float2*)stim, (float2*)out);
    } else {
        int T = 1000;
        int N = in_sizes[0] / T;
        int threads = 128;
        int blocks = (N + threads - 1) / threads;
        lif_kernel_generic<<<blocks, threads>>>(stim, out, N, T);
    }
}